// round 14
// baseline (speedup 1.0000x reference)
#include <cuda_runtime.h>
#include <cuda_bf16.h>
#include <math.h>
#include <stdint.h>

// ---------------------------------------------------------------------------
// Problem constants
// ---------------------------------------------------------------------------
#define BB   2
#define LQ   12240
#define DMO  256
#define MH   8
#define ROWS (BB * LQ)     // 24480

__device__ __constant__ int c_H[4]  = {96, 48, 24, 12};
__device__ __constant__ int c_W[4]  = {96, 48, 24, 12};
__device__ __constant__ int c_ST[4] = {0, 9216, 11520, 12096};

// ---------------------------------------------------------------------------
// Scratch (static device globals: allocation-free, graph-safe)
// ---------------------------------------------------------------------------
__device__ float g_value[ROWS * DMO];
__device__ float g_offs [ROWS * DMO];
__device__ float g_alog [ROWS * 128];

// pre-split bf16 fragment-layout buffers (uint4 slots)
__device__ uint4 g_inpf_sp [ROWS * 64];
__device__ uint4 g_query_sp[ROWS * 64];
__device__ uint4 g_msout_sp[ROWS * 64];
__device__ uint4 g_Wv_sp[64 * 256];
__device__ uint4 g_Ws_sp[64 * 256];
__device__ uint4 g_Wa_sp[64 * 128];
__device__ uint4 g_Wo_sp[64 * 256];

// ---------------------------------------------------------------------------
// bf16 split: hi = truncate-to-bf16 (exact residual), lo = rn(a-hi).
// ---------------------------------------------------------------------------
__device__ __forceinline__ uint4 split_pack(float2 p0, float2 p1) {
    uint32_t h0 = __float_as_uint(p0.x) & 0xFFFF0000u;
    uint32_t h1 = __float_as_uint(p0.y) & 0xFFFF0000u;
    uint32_t h2 = __float_as_uint(p1.x) & 0xFFFF0000u;
    uint32_t h3 = __float_as_uint(p1.y) & 0xFFFF0000u;
    float l0 = p0.x - __uint_as_float(h0);
    float l1 = p0.y - __uint_as_float(h1);
    float l2 = p1.x - __uint_as_float(h2);
    float l3 = p1.y - __uint_as_float(h3);
    uint4 r;
    r.x = __byte_perm(h0, h1, 0x7632);
    asm("cvt.rn.bf16x2.f32 %0, %1, %2;" : "=r"(r.y) : "f"(l1), "f"(l0));
    r.z = __byte_perm(h2, h3, 0x7632);
    asm("cvt.rn.bf16x2.f32 %0, %1, %2;" : "=r"(r.w) : "f"(l3), "f"(l2));
    return r;
}

__device__ __forceinline__ void mma_bf16(float4& c,
                                         uint32_t a0, uint32_t a1, uint32_t a2, uint32_t a3,
                                         uint32_t b0, uint32_t b1) {
    asm volatile(
        "mma.sync.aligned.m16n8k16.row.col.f32.bf16.bf16.f32 "
        "{%0,%1,%2,%3}, {%4,%5,%6,%7}, {%8,%9}, {%0,%1,%2,%3};"
        : "+f"(c.x), "+f"(c.y), "+f"(c.z), "+f"(c.w)
        : "r"(a0), "r"(a1), "r"(a2), "r"(a3), "r"(b0), "r"(b1));
}

__device__ __forceinline__ uint32_t smem_u32(const void* p) {
    uint32_t a;
    asm("{ .reg .u64 t; cvta.to.shared.u64 t, %1; cvt.u32.u64 %0, t; }"
        : "=r"(a) : "l"(p));
    return a;
}

__device__ __forceinline__ void cp16(uint32_t smem, const void* gmem, uint32_t sz) {
    asm volatile("cp.async.cg.shared.global [%0], [%1], 16, %2;"
                 :: "r"(smem), "l"(gmem), "r"(sz) : "memory");
}
#define CP_COMMIT() asm volatile("cp.async.commit_group;" ::: "memory")
#define CP_WAIT(n)  asm volatile("cp.async.wait_group %0;" :: "n"(n) : "memory")

#define LDG4_NC(dst, ptr)                                                     \
    asm volatile("ld.global.nc.v4.f32 {%0,%1,%2,%3}, [%4];"                   \
                 : "=f"((dst).x), "=f"((dst).y), "=f"((dst).z), "=f"((dst).w) \
                 : "l"(ptr))

// ---------------------------------------------------------------------------
// Pre-convert A-style matrices [rows x 256] f32 -> fragment-layout uint4.
// ---------------------------------------------------------------------------
__global__ void __launch_bounds__(256)
convert_A2(const float* __restrict__ A0, uint4* __restrict__ D0,
           const float* __restrict__ A1, uint4* __restrict__ D1, int rows)
{
    const float* src = blockIdx.y ? A1 : A0;
    uint4*       dst = blockIdx.y ? D1 : D0;
    int g = blockIdx.x * 256 + threadIdx.x;
    if (g >= rows * 64) return;
    int row  = g >> 6;
    int rest = g & 63;
    int chunk = rest >> 3;
    int s = (rest >> 2) & 1;
    int t = rest & 3;
    const float* p = src + (size_t)row * 256 + chunk * 32 + s * 16 + 2 * t;
    float2 p0 = *(const float2*)p;
    float2 p1 = *(const float2*)(p + 8);
    dst[g] = split_pack(p0, p1);
}

// ---------------------------------------------------------------------------
// Pre-convert weights [256 x ncols] f32 -> B fragment layout.
// ---------------------------------------------------------------------------
__global__ void __launch_bounds__(256)
convert_W4(const float* __restrict__ W0, uint4* __restrict__ D0, int n0,
           const float* __restrict__ W1, uint4* __restrict__ D1, int n1,
           const float* __restrict__ W2, uint4* __restrict__ D2, int n2,
           const float* __restrict__ W3, uint4* __restrict__ D3, int n3)
{
    const float* Wm; uint4* D; int ncols;
    switch (blockIdx.y) {
        case 0:  Wm = W0; D = D0; ncols = n0; break;
        case 1:  Wm = W1; D = D1; ncols = n1; break;
        case 2:  Wm = W2; D = D2; ncols = n2; break;
        default: Wm = W3; D = D3; ncols = n3; break;
    }
    int g = blockIdx.x * 256 + threadIdx.x;
    if (g >= 64 * ncols) return;
    int n    = g % ncols;
    int rest = g / ncols;
    int chunk = rest >> 3;
    int s = (rest >> 2) & 1;
    int t = rest & 3;
    int k = chunk * 32 + s * 16 + 2 * t;
    const float* p = Wm + (size_t)k * ncols + n;
    float2 p0 = make_float2(p[0], p[ncols]);
    float2 p1 = make_float2(p[8 * ncols], p[9 * ncols]);
    D[(size_t)(chunk * ncols + n) * 8 + s * 4 + t] = split_pack(p0, p1);
}

// ---------------------------------------------------------------------------
// Pre-split bf16 3-term GEMM + bias. Block tile 128x128, 8 warps = 4(M)x2(N),
// warp tile 32x64. K chunk 32, double-buffered cp.async.
// tileOff: row-tile offset (for split-row pipelined launches).
// ---------------------------------------------------------------------------
#define STAGE_U4   3072
#define GEMM_SMEM  (2 * STAGE_U4 * 16)   // 98304 B

__global__ void __launch_bounds__(256)
gemm_split(const uint4* __restrict__ A0, const uint4* __restrict__ P0,
           const float* __restrict__ b0, float* __restrict__ C0, int nc0, int yt0,
           const uint4* __restrict__ A1, const uint4* __restrict__ P1,
           const float* __restrict__ b1, float* __restrict__ C1, int nc1, int yt1,
           const uint4* __restrict__ A2, const uint4* __restrict__ P2,
           const float* __restrict__ b2, float* __restrict__ C2, int nc2,
           int rows, int tileOff)
{
    extern __shared__ uint4 sm[];

    const int y = blockIdx.y;
    const uint4 *Asp, *Wsp;  const float* bias;  float* C;  int ncols, colBase;
    if (y < yt0) {
        Asp = A0; Wsp = P0; bias = b0; C = C0; ncols = nc0; colBase = y * 128;
    } else if (y < yt0 + yt1) {
        Asp = A1; Wsp = P1; bias = b1; C = C1; ncols = nc1; colBase = (y - yt0) * 128;
    } else {
        Asp = A2; Wsp = P2; bias = b2; C = C2; ncols = nc2; colBase = (y - yt0 - yt1) * 128;
    }

    const int tid  = threadIdx.x;
    const int lane = tid & 31;
    const int wid  = tid >> 5;
    const int wm   = wid & 3;
    const int wn   = wid >> 2;
    const int r    = lane >> 2;
    const int tig  = lane & 3;
    const int rowBase = (blockIdx.x + tileOff) * 128;

    const uint32_t smem_base = smem_u32(sm);
    const int a_row  = tid >> 3;
    const int a_slot = tid & 7;

    float4 acc[2][8];
    #pragma unroll
    for (int mt = 0; mt < 2; mt++)
        #pragma unroll
        for (int nt = 0; nt < 8; nt++)
            acc[mt][nt] = make_float4(0.f, 0.f, 0.f, 0.f);

#define LOAD_CHUNK(KB, ST)                                                    \
    do {                                                                      \
        const uint32_t _base = smem_base + (ST) * (STAGE_U4 * 16);            \
        _Pragma("unroll")                                                     \
        for (int it = 0; it < 4; it++) {                                      \
            int row  = a_row + it * 32;                                       \
            int grow = rowBase + row;                                         \
            cp16(_base + (uint32_t)(row * 12 + a_slot) * 16,                  \
                 Asp + ((size_t)grow * 64 + (KB) * 8 + a_slot),               \
                 (grow < rows) ? 16u : 0u);                                   \
        }                                                                     \
        _Pragma("unroll")                                                     \
        for (int it = 0; it < 4; it++) {                                      \
            int n = a_row + it * 32;                                          \
            cp16(_base + (uint32_t)(1536 + n * 12 + a_slot) * 16,             \
                 Wsp + ((size_t)((KB) * ncols + colBase + n) * 8 + a_slot), 16u); \
        }                                                                     \
        CP_COMMIT();                                                          \
    } while (0)

    LOAD_CHUNK(0, 0);

    for (int kb = 0; kb < 8; kb++) {
        if (kb < 7) {
            LOAD_CHUNK(kb + 1, (kb + 1) & 1);
            CP_WAIT(1);
        } else {
            CP_WAIT(0);
        }
        __syncthreads();

        const uint4* As4 = sm + (kb & 1) * STAGE_U4;
        const uint4* Bs4 = As4 + 1536;

        #pragma unroll
        for (int s = 0; s < 2; s++) {
            uint4 aw[2][2];
            #pragma unroll
            for (int mt = 0; mt < 2; mt++) {
                const int ar = wm * 32 + mt * 16 + r;
                aw[mt][0] = As4[ar * 12 + s * 4 + tig];
                aw[mt][1] = As4[(ar + 8) * 12 + s * 4 + tig];
            }
            #pragma unroll
            for (int nt = 0; nt < 8; nt++) {
                uint4 bw = Bs4[(wn * 64 + nt * 8 + r) * 12 + s * 4 + tig];
                #pragma unroll
                for (int mt = 0; mt < 2; mt++) {
                    mma_bf16(acc[mt][nt], aw[mt][0].x, aw[mt][1].x, aw[mt][0].z, aw[mt][1].z, bw.x, bw.z);
                    mma_bf16(acc[mt][nt], aw[mt][0].y, aw[mt][1].y, aw[mt][0].w, aw[mt][1].w, bw.x, bw.z);
                    mma_bf16(acc[mt][nt], aw[mt][0].x, aw[mt][1].x, aw[mt][0].z, aw[mt][1].z, bw.y, bw.w);
                }
            }
        }
        __syncthreads();
    }
#undef LOAD_CHUNK

    #pragma unroll
    for (int nt = 0; nt < 8; nt++) {
        const int col = colBase + wn * 64 + nt * 8 + tig * 2;
        const float bb0 = bias[col], bb1 = bias[col + 1];
        #pragma unroll
        for (int mt = 0; mt < 2; mt++) {
            const int row0 = rowBase + wm * 32 + mt * 16 + r;
            const float4 c4 = acc[mt][nt];
            if (row0 < rows)
                *(float2*)(C + (size_t)row0 * ncols + col) =
                    make_float2(c4.x + bb0, c4.y + bb1);
            if (row0 + 8 < rows)
                *(float2*)(C + (size_t)(row0 + 8) * ncols + col) =
                    make_float2(c4.z + bb0, c4.w + bb1);
        }
    }
}

// ---------------------------------------------------------------------------
// Fused softmax + deformable bilinear sampling.
// __launch_bounds__(256, 3): allow ~85 regs so the 8 ordered LDG.128 stay
// in flight (ptxas previously clamped to 32 regs / serialized loads).
// rowOff: row offset for split-batch pipelined launches.
// ---------------------------------------------------------------------------
__global__ void __launch_bounds__(256, 3)
sample_kernel(const float* __restrict__ value,
              const float* __restrict__ offs,
              const float* __restrict__ alog,
              const float* __restrict__ refp,
              uint4* __restrict__ msout_sp,
              int rowOff)
{
    __shared__ int4   sIdx[8][16];
    __shared__ float4 sWt [8][16];

    const int wid  = threadIdx.x >> 5;
    const int lane = threadIdx.x & 31;
    const int m    = wid;
    const int row  = blockIdx.x + rowOff;
    const int b    = (row >= LQ) ? 1 : 0;

    // ---- softmax over 16 (l,p) logits ----
    const float* lg = alog + (size_t)row * 128 + m * 16;
    float v = (lane < 16) ? lg[lane] : -1e30f;
    float mx = v;
    #pragma unroll
    for (int o = 16; o; o >>= 1) mx = fmaxf(mx, __shfl_xor_sync(0xffffffffu, mx, o));
    float e = (lane < 16) ? expf(v - mx) : 0.f;
    float s = e;
    #pragma unroll
    for (int o = 16; o; o >>= 1) s += __shfl_xor_sync(0xffffffffu, s, o);
    const float inv = 1.f / s;

    // ---- per-point setup ----
    if (lane < 16) {
        const int l  = lane >> 2;
        const int H  = c_H[l];
        const int W  = c_W[l];
        const int st = c_ST[l];
        const float fW = (float)W, fH = (float)H;

        const float rx = refp[(row * 4 + l) * 2 + 0];
        const float ry = refp[(row * 4 + l) * 2 + 1];
        const float* od = offs + (size_t)row * 256 + m * 32 + lane * 2;
        const float ox = od[0], oy = od[1];

        const float x = fmaf(rx, fW, ox) - 0.5f;
        const float y = fmaf(ry, fH, oy) - 0.5f;

        const float x0f = floorf(x), y0f = floorf(y);
        const float fx = x - x0f, fy = y - y0f;
        const int ix = (int)x0f, iy = (int)y0f;

        const float lw = e * inv;
        float w00 = (1.f - fx) * (1.f - fy) * lw;
        float w01 = fx * (1.f - fy) * lw;
        float w10 = (1.f - fx) * fy * lw;
        float w11 = fx * fy * lw;

        const bool vx0 = (ix >= 0) && (ix < W);
        const bool vx1 = (ix + 1 >= 0) && (ix + 1 < W);
        const bool vy0 = (iy >= 0) && (iy < H);
        const bool vy1 = (iy + 1 >= 0) && (iy + 1 < H);
        if (!(vx0 && vy0)) w00 = 0.f;
        if (!(vx1 && vy0)) w01 = 0.f;
        if (!(vx0 && vy1)) w10 = 0.f;
        if (!(vx1 && vy1)) w11 = 0.f;

        const int cx0 = min(max(ix, 0), W - 1);
        const int cx1 = min(max(ix + 1, 0), W - 1);
        const int cy0 = min(max(iy, 0), H - 1);
        const int cy1 = min(max(iy + 1, 0), H - 1);
        const int r0 = st + cy0 * W;
        const int r1 = st + cy1 * W;

        sIdx[wid][lane] = make_int4((r0 + cx0) * 256, (r0 + cx1) * 256,
                                    (r1 + cx0) * 256, (r1 + cx1) * 256);
        sWt [wid][lane] = make_float4(w00, w01, w10, w11);
    }
    __syncwarp();

    // ---- gather: group g (8 lanes, float4 = 32 channels), 2 points/batch ----
    const int g  = lane >> 3;
    const int c4 = (lane & 7) * 4;
    const float* vb4 = value + (size_t)b * LQ * 256 + m * 32 + c4;

    float4 acc = make_float4(0.f, 0.f, 0.f, 0.f);
    #pragma unroll
    for (int h = 0; h < 2; h++) {
        const int pa = g * 4 + h * 2;
        const int4   Ia = sIdx[wid][pa];
        const int4   Ib = sIdx[wid][pa + 1];
        const float4 Wa_ = sWt[wid][pa];
        const float4 Wb_ = sWt[wid][pa + 1];
        float4 a0, a1, a2, a3, b0, b1, b2, b3;
        LDG4_NC(a0, vb4 + Ia.x);
        LDG4_NC(a1, vb4 + Ia.y);
        LDG4_NC(a2, vb4 + Ia.z);
        LDG4_NC(a3, vb4 + Ia.w);
        LDG4_NC(b0, vb4 + Ib.x);
        LDG4_NC(b1, vb4 + Ib.y);
        LDG4_NC(b2, vb4 + Ib.z);
        LDG4_NC(b3, vb4 + Ib.w);
        acc.x = fmaf(Wa_.x, a0.x, fmaf(Wa_.y, a1.x, fmaf(Wa_.z, a2.x, fmaf(Wa_.w, a3.x, acc.x))));
        acc.y = fmaf(Wa_.x, a0.y, fmaf(Wa_.y, a1.y, fmaf(Wa_.z, a2.y, fmaf(Wa_.w, a3.y, acc.y))));
        acc.z = fmaf(Wa_.x, a0.z, fmaf(Wa_.y, a1.z, fmaf(Wa_.z, a2.z, fmaf(Wa_.w, a3.z, acc.z))));
        acc.w = fmaf(Wa_.x, a0.w, fmaf(Wa_.y, a1.w, fmaf(Wa_.z, a2.w, fmaf(Wa_.w, a3.w, acc.w))));
        acc.x = fmaf(Wb_.x, b0.x, fmaf(Wb_.y, b1.x, fmaf(Wb_.z, b2.x, fmaf(Wb_.w, b3.x, acc.x))));
        acc.y = fmaf(Wb_.x, b0.y, fmaf(Wb_.y, b1.y, fmaf(Wb_.z, b2.y, fmaf(Wb_.w, b3.y, acc.y))));
        acc.z = fmaf(Wb_.x, b0.z, fmaf(Wb_.y, b1.z, fmaf(Wb_.z, b2.z, fmaf(Wb_.w, b3.z, acc.z))));
        acc.w = fmaf(Wb_.x, b0.w, fmaf(Wb_.y, b1.w, fmaf(Wb_.z, b2.w, fmaf(Wb_.w, b3.w, acc.w))));
    }

    // ---- butterfly over the 4 groups ----
    #pragma unroll
    for (int o = 8; o <= 16; o <<= 1) {
        acc.x += __shfl_xor_sync(0xffffffffu, acc.x, o);
        acc.y += __shfl_xor_sync(0xffffffffu, acc.y, o);
        acc.z += __shfl_xor_sync(0xffffffffu, acc.z, o);
        acc.w += __shfl_xor_sync(0xffffffffu, acc.w, o);
    }

    // ---- fused epilogue: emit bf16-split fragment slot directly ----
    {
        const int j  = lane & 7;
        const int sI = (j >> 2) & 1;
        const int tI = j & 3;
        const int src0 = 4 * sI + (tI >> 1);
        const int src1 = src0 + 2;

        float x0 = __shfl_sync(0xffffffffu, acc.x, src0);
        float y0 = __shfl_sync(0xffffffffu, acc.y, src0);
        float z0 = __shfl_sync(0xffffffffu, acc.z, src0);
        float w0 = __shfl_sync(0xffffffffu, acc.w, src0);
        float x1 = __shfl_sync(0xffffffffu, acc.x, src1);
        float y1 = __shfl_sync(0xffffffffu, acc.y, src1);
        float z1 = __shfl_sync(0xffffffffu, acc.z, src1);
        float w1 = __shfl_sync(0xffffffffu, acc.w, src1);

        const bool odd = (tI & 1);
        float2 p0 = odd ? make_float2(z0, w0) : make_float2(x0, y0);
        float2 p1 = odd ? make_float2(z1, w1) : make_float2(x1, y1);

        if (lane < 8)
            msout_sp[(size_t)row * 64 + m * 8 + j] = split_pack(p0, p1);
    }
}

// ---------------------------------------------------------------------------
// Launch: stream-pipelined across the batch dimension.
//   S1 (capture stream): converts -> GEMMs (split by row half) -> final GEMMs
//   S2: samplers per batch, overlapped with S1's b1 GEMMs / b0 final GEMM.
// Event fork/join is graph-capture legal. Streams/events are created fresh
// per call (host-side only; kernel_launch is invoked O(1) times).
// ---------------------------------------------------------------------------
extern "C" void kernel_launch(void* const* d_in, const int* in_sizes, int n_in,
                              void* d_out, int out_size)
{
    (void)in_sizes; (void)n_in; (void)out_size;

    const float* query = (const float*)d_in[0];
    const float* refp  = (const float*)d_in[1];
    const float* inpf  = (const float*)d_in[2];
    const float* Wv = (const float*)d_in[4];
    const float* bv = (const float*)d_in[5];
    const float* Ws = (const float*)d_in[6];
    const float* bs = (const float*)d_in[7];
    const float* Wa = (const float*)d_in[8];
    const float* ba = (const float*)d_in[9];
    const float* Wo = (const float*)d_in[10];
    const float* bo = (const float*)d_in[11];
    float* out = (float*)d_out;

    float *value, *offs, *alog;
    uint4 *inpf_sp, *query_sp, *msout_sp, *Wv_sp, *Ws_sp, *Wa_sp, *Wo_sp;
    cudaGetSymbolAddress((void**)&value, g_value);
    cudaGetSymbolAddress((void**)&offs,  g_offs);
    cudaGetSymbolAddress((void**)&alog,  g_alog);
    cudaGetSymbolAddress((void**)&inpf_sp,  g_inpf_sp);
    cudaGetSymbolAddress((void**)&query_sp, g_query_sp);
    cudaGetSymbolAddress((void**)&msout_sp, g_msout_sp);
    cudaGetSymbolAddress((void**)&Wv_sp, g_Wv_sp);
    cudaGetSymbolAddress((void**)&Ws_sp, g_Ws_sp);
    cudaGetSymbolAddress((void**)&Wa_sp, g_Wa_sp);
    cudaGetSymbolAddress((void**)&Wo_sp, g_Wo_sp);

    cudaFuncSetAttribute(gemm_split, cudaFuncAttributeMaxDynamicSharedMemorySize,
                         GEMM_SMEM);

    cudaStream_t s2;
    cudaEvent_t ev0, ev1, es0, es1;
    cudaStreamCreateWithFlags(&s2, cudaStreamNonBlocking);
    cudaEventCreateWithFlags(&ev0, cudaEventDisableTiming);
    cudaEventCreateWithFlags(&ev1, cudaEventDisableTiming);
    cudaEventCreateWithFlags(&es0, cudaEventDisableTiming);
    cudaEventCreateWithFlags(&es1, cudaEventDisableTiming);

    const dim3 blk(256);
    const int  aBlocks = ROWS * 64 / 256;          // 6120

    // -- S1: converts --
    convert_W4<<<dim3(64, 4), blk>>>(Wv, Wv_sp, 256, Ws, Ws_sp, 256,
                                     Wa, Wa_sp, 128, Wo, Wo_sp, 256);
    convert_A2<<<dim3(aBlocks, 2), blk>>>(inpf, inpf_sp, query, query_sp, ROWS);

    // -- S1: batch-0 producer GEMMs (tiles 0..95 cover rows 0..12287) --
    gemm_split<<<dim3(96, 2), blk, GEMM_SMEM>>>(
        inpf_sp, Wv_sp, bv, value, 256, 2,
        inpf_sp, Wv_sp, bv, value, 256, 0,
        inpf_sp, Wv_sp, bv, value, 256, ROWS, 0);
    gemm_split<<<dim3(96, 3), blk, GEMM_SMEM>>>(
        query_sp, Ws_sp, bs, offs, 256, 2,
        query_sp, Wa_sp, ba, alog, 128, 1,
        query_sp, Ws_sp, bs, offs, 256, ROWS, 0);
    cudaEventRecord(ev0, 0);

    // -- S1: batch-1 producer GEMMs (tiles 96..191) --
    gemm_split<<<dim3(96, 2), blk, GEMM_SMEM>>>(
        inpf_sp, Wv_sp, bv, value, 256, 2,
        inpf_sp, Wv_sp, bv, value, 256, 0,
        inpf_sp, Wv_sp, bv, value, 256, ROWS, 96);
    gemm_split<<<dim3(96, 3), blk, GEMM_SMEM>>>(
        query_sp, Ws_sp, bs, offs, 256, 2,
        query_sp, Wa_sp, ba, alog, 128, 1,
        query_sp, Ws_sp, bs, offs, 256, ROWS, 96);
    cudaEventRecord(ev1, 0);

    // -- S2: samplers per batch (fork from S1) --
    cudaStreamWaitEvent(s2, ev0, 0);
    sample_kernel<<<LQ, blk, 0, s2>>>(value, offs, alog, refp, msout_sp, 0);
    cudaEventRecord(es0, s2);
    cudaStreamWaitEvent(s2, ev1, 0);
    sample_kernel<<<LQ, blk, 0, s2>>>(value, offs, alog, refp, msout_sp, LQ);
    cudaEventRecord(es1, s2);

    // -- S1: final GEMMs (join) --
    // tiles 0..94 -> rows 0..12159 (pure batch-0 msout)
    cudaStreamWaitEvent(0, es0, 0);
    gemm_split<<<dim3(95, 2), blk, GEMM_SMEM>>>(
        msout_sp, Wo_sp, bo, out, 256, 2,
        msout_sp, Wo_sp, bo, out, 256, 0,
        msout_sp, Wo_sp, bo, out, 256, ROWS, 0);
    // tiles 95..191 -> rows 12160..24479 (needs both sampler halves)
    cudaStreamWaitEvent(0, es1, 0);
    gemm_split<<<dim3(97, 2), blk, GEMM_SMEM>>>(
        msout_sp, Wo_sp, bo, out, 256, 2,
        msout_sp, Wo_sp, bo, out, 256, 0,
        msout_sp, Wo_sp, bo, out, 256, ROWS, 95);
}

// round 15
// speedup vs baseline: 1.3239x; 1.3239x over previous
#include <cuda_runtime.h>
#include <cuda_bf16.h>
#include <cuda_fp16.h>
#include <math.h>
#include <stdint.h>

// ---------------------------------------------------------------------------
// Problem constants
// ---------------------------------------------------------------------------
#define BB   2
#define LQ   12240
#define DMO  256
#define MH   8
#define ROWS (BB * LQ)     // 24480

__device__ __constant__ int c_H[4]  = {96, 48, 24, 12};
__device__ __constant__ int c_W[4]  = {96, 48, 24, 12};
__device__ __constant__ int c_ST[4] = {0, 9216, 11520, 12096};

// ---------------------------------------------------------------------------
// Scratch (static device globals: allocation-free, graph-safe)
// ---------------------------------------------------------------------------
__device__ float g_value[ROWS * DMO];
__device__ float g_offs [ROWS * DMO];
__device__ float g_alog [ROWS * 128];

// pre-split fp16 fragment-layout buffers (uint4 slots)
__device__ uint4 g_inpf_sp [ROWS * 64];
__device__ uint4 g_query_sp[ROWS * 64];
__device__ uint4 g_msout_sp[ROWS * 64];
__device__ uint4 g_Wv_sp[64 * 256];
__device__ uint4 g_Ws_sp[64 * 256];
__device__ uint4 g_Wa_sp[64 * 128];
__device__ uint4 g_Wo_sp[64 * 256];

// ---------------------------------------------------------------------------
// fp16 split: hi = rn-to-fp16, lo = rn(a - hi)  (|lo| <= 2^-12 |a| before rn;
// combined Ah+Al carries ~22 mantissa bits).
// Slot = {P0h, P0l, P1h, P1l}; P0 = k{2t,2t+1}, P1 = k{8+2t,8+2t+1},
// packed half2 with even-k element in the LOW half.
// ---------------------------------------------------------------------------
__device__ __forceinline__ uint32_t h2u(__half2 h) {
    uint32_t u;
    *(__half2*)&u = h;
    return u;
}

__device__ __forceinline__ uint4 split_pack(float2 p0, float2 p1) {
    __half2 H0 = __floats2half2_rn(p0.x, p0.y);     // .x (low) = even-k
    __half2 H1 = __floats2half2_rn(p1.x, p1.y);
    float2 hf0 = __half22float2(H0);
    float2 hf1 = __half22float2(H1);
    __half2 L0 = __floats2half2_rn(p0.x - hf0.x, p0.y - hf0.y);
    __half2 L1 = __floats2half2_rn(p1.x - hf1.x, p1.y - hf1.y);
    uint4 r;
    r.x = h2u(H0);
    r.y = h2u(L0);
    r.z = h2u(H1);
    r.w = h2u(L1);
    return r;
}

// m16n8k16 fp16 MMA: D(16x8,f32) += A(16x16) * B(16x8)
__device__ __forceinline__ void mma_f16(float4& c,
                                        uint32_t a0, uint32_t a1, uint32_t a2, uint32_t a3,
                                        uint32_t b0, uint32_t b1) {
    asm volatile(
        "mma.sync.aligned.m16n8k16.row.col.f32.f16.f16.f32 "
        "{%0,%1,%2,%3}, {%4,%5,%6,%7}, {%8,%9}, {%0,%1,%2,%3};"
        : "+f"(c.x), "+f"(c.y), "+f"(c.z), "+f"(c.w)
        : "r"(a0), "r"(a1), "r"(a2), "r"(a3), "r"(b0), "r"(b1));
}

__device__ __forceinline__ uint32_t smem_u32(const void* p) {
    uint32_t a;
    asm("{ .reg .u64 t; cvta.to.shared.u64 t, %1; cvt.u32.u64 %0, t; }"
        : "=r"(a) : "l"(p));
    return a;
}

__device__ __forceinline__ void cp16(uint32_t smem, const void* gmem, uint32_t sz) {
    asm volatile("cp.async.cg.shared.global [%0], [%1], 16, %2;"
                 :: "r"(smem), "l"(gmem), "r"(sz) : "memory");
}
#define CP_COMMIT() asm volatile("cp.async.commit_group;" ::: "memory")
#define CP_WAIT(n)  asm volatile("cp.async.wait_group %0;" :: "n"(n) : "memory")

#define LDG4_NC(dst, ptr)                                                     \
    asm volatile("ld.global.nc.v4.f32 {%0,%1,%2,%3}, [%4];"                   \
                 : "=f"((dst).x), "=f"((dst).y), "=f"((dst).z), "=f"((dst).w) \
                 : "l"(ptr))

// ---------------------------------------------------------------------------
// Pre-convert A-style matrices [rows x 256] f32 -> fragment-layout uint4.
// ---------------------------------------------------------------------------
__global__ void __launch_bounds__(256)
convert_A2(const float* __restrict__ A0, uint4* __restrict__ D0,
           const float* __restrict__ A1, uint4* __restrict__ D1, int rows)
{
    const float* src = blockIdx.y ? A1 : A0;
    uint4*       dst = blockIdx.y ? D1 : D0;
    int g = blockIdx.x * 256 + threadIdx.x;
    if (g >= rows * 64) return;
    int row  = g >> 6;
    int rest = g & 63;
    int chunk = rest >> 3;
    int s = (rest >> 2) & 1;
    int t = rest & 3;
    const float* p = src + (size_t)row * 256 + chunk * 32 + s * 16 + 2 * t;
    float2 p0 = *(const float2*)p;
    float2 p1 = *(const float2*)(p + 8);
    dst[g] = split_pack(p0, p1);
}

// ---------------------------------------------------------------------------
// Pre-convert weights [256 x ncols] f32 -> B fragment layout.
// ---------------------------------------------------------------------------
__global__ void __launch_bounds__(256)
convert_W4(const float* __restrict__ W0, uint4* __restrict__ D0, int n0,
           const float* __restrict__ W1, uint4* __restrict__ D1, int n1,
           const float* __restrict__ W2, uint4* __restrict__ D2, int n2,
           const float* __restrict__ W3, uint4* __restrict__ D3, int n3)
{
    const float* Wm; uint4* D; int ncols;
    switch (blockIdx.y) {
        case 0:  Wm = W0; D = D0; ncols = n0; break;
        case 1:  Wm = W1; D = D1; ncols = n1; break;
        case 2:  Wm = W2; D = D2; ncols = n2; break;
        default: Wm = W3; D = D3; ncols = n3; break;
    }
    int g = blockIdx.x * 256 + threadIdx.x;
    if (g >= 64 * ncols) return;
    int n    = g % ncols;
    int rest = g / ncols;
    int chunk = rest >> 3;
    int s = (rest >> 2) & 1;
    int t = rest & 3;
    int k = chunk * 32 + s * 16 + 2 * t;
    const float* p = Wm + (size_t)k * ncols + n;
    float2 p0 = make_float2(p[0], p[ncols]);
    float2 p1 = make_float2(p[8 * ncols], p[9 * ncols]);
    D[(size_t)(chunk * ncols + n) * 8 + s * 4 + t] = split_pack(p0, p1);
}

// ---------------------------------------------------------------------------
// Pre-split fp16 2-term GEMM + bias:  D = Ah*Bh + Al*Bh  (= A * Bh;
// dropped A*Bl term is ~2^-12 relative).
// Block tile 128x128, 8 warps = 4(M) x 2(N), warp tile 32x64. K chunk 32,
// double-buffered cp.async. Triple-set y-dispatch.
// ---------------------------------------------------------------------------
#define STAGE_U4   3072
#define GEMM_SMEM  (2 * STAGE_U4 * 16)   // 98304 B

__global__ void __launch_bounds__(256)
gemm_split(const uint4* __restrict__ A0, const uint4* __restrict__ P0,
           const float* __restrict__ b0, float* __restrict__ C0, int nc0, int yt0,
           const uint4* __restrict__ A1, const uint4* __restrict__ P1,
           const float* __restrict__ b1, float* __restrict__ C1, int nc1, int yt1,
           const uint4* __restrict__ A2, const uint4* __restrict__ P2,
           const float* __restrict__ b2, float* __restrict__ C2, int nc2,
           int rows)
{
    extern __shared__ uint4 sm[];

    const int y = blockIdx.y;
    const uint4 *Asp, *Wsp;  const float* bias;  float* C;  int ncols, colBase;
    if (y < yt0) {
        Asp = A0; Wsp = P0; bias = b0; C = C0; ncols = nc0; colBase = y * 128;
    } else if (y < yt0 + yt1) {
        Asp = A1; Wsp = P1; bias = b1; C = C1; ncols = nc1; colBase = (y - yt0) * 128;
    } else {
        Asp = A2; Wsp = P2; bias = b2; C = C2; ncols = nc2; colBase = (y - yt0 - yt1) * 128;
    }

    const int tid  = threadIdx.x;
    const int lane = tid & 31;
    const int wid  = tid >> 5;
    const int wm   = wid & 3;
    const int wn   = wid >> 2;
    const int r    = lane >> 2;
    const int tig  = lane & 3;
    const int rowBase = blockIdx.x * 128;

    const uint32_t smem_base = smem_u32(sm);
    const int a_row  = tid >> 3;
    const int a_slot = tid & 7;

    float4 acc[2][8];
    #pragma unroll
    for (int mt = 0; mt < 2; mt++)
        #pragma unroll
        for (int nt = 0; nt < 8; nt++)
            acc[mt][nt] = make_float4(0.f, 0.f, 0.f, 0.f);

#define LOAD_CHUNK(KB, ST)                                                    \
    do {                                                                      \
        const uint32_t _base = smem_base + (ST) * (STAGE_U4 * 16);            \
        _Pragma("unroll")                                                     \
        for (int it = 0; it < 4; it++) {                                      \
            int row  = a_row + it * 32;                                       \
            int grow = rowBase + row;                                         \
            cp16(_base + (uint32_t)(row * 12 + a_slot) * 16,                  \
                 Asp + ((size_t)grow * 64 + (KB) * 8 + a_slot),               \
                 (grow < rows) ? 16u : 0u);                                   \
        }                                                                     \
        _Pragma("unroll")                                                     \
        for (int it = 0; it < 4; it++) {                                      \
            int n = a_row + it * 32;                                          \
            cp16(_base + (uint32_t)(1536 + n * 12 + a_slot) * 16,             \
                 Wsp + ((size_t)((KB) * ncols + colBase + n) * 8 + a_slot), 16u); \
        }                                                                     \
        CP_COMMIT();                                                          \
    } while (0)

    LOAD_CHUNK(0, 0);

    for (int kb = 0; kb < 8; kb++) {
        if (kb < 7) {
            LOAD_CHUNK(kb + 1, (kb + 1) & 1);
            CP_WAIT(1);
        } else {
            CP_WAIT(0);
        }
        __syncthreads();

        const uint4* As4 = sm + (kb & 1) * STAGE_U4;
        const uint4* Bs4 = As4 + 1536;

        #pragma unroll
        for (int s = 0; s < 2; s++) {
            uint4 aw[2][2];
            #pragma unroll
            for (int mt = 0; mt < 2; mt++) {
                const int ar = wm * 32 + mt * 16 + r;
                aw[mt][0] = As4[ar * 12 + s * 4 + tig];
                aw[mt][1] = As4[(ar + 8) * 12 + s * 4 + tig];
            }
            #pragma unroll
            for (int nt = 0; nt < 8; nt++) {
                uint4 bw = Bs4[(wn * 64 + nt * 8 + r) * 12 + s * 4 + tig];
                #pragma unroll
                for (int mt = 0; mt < 2; mt++) {
                    // hi*hi + lo*hi  ==  (Ah+Al) * Bh
                    mma_f16(acc[mt][nt], aw[mt][0].x, aw[mt][1].x, aw[mt][0].z, aw[mt][1].z, bw.x, bw.z);
                    mma_f16(acc[mt][nt], aw[mt][0].y, aw[mt][1].y, aw[mt][0].w, aw[mt][1].w, bw.x, bw.z);
                }
            }
        }
        __syncthreads();
    }
#undef LOAD_CHUNK

    // ---- epilogue: +bias, float2 stores ----
    #pragma unroll
    for (int nt = 0; nt < 8; nt++) {
        const int col = colBase + wn * 64 + nt * 8 + tig * 2;
        const float bb0 = bias[col], bb1 = bias[col + 1];
        #pragma unroll
        for (int mt = 0; mt < 2; mt++) {
            const int row0 = rowBase + wm * 32 + mt * 16 + r;
            const float4 c4 = acc[mt][nt];
            if (row0 < rows)
                *(float2*)(C + (size_t)row0 * ncols + col) =
                    make_float2(c4.x + bb0, c4.y + bb1);
            if (row0 + 8 < rows)
                *(float2*)(C + (size_t)(row0 + 8) * ncols + col) =
                    make_float2(c4.z + bb0, c4.w + bb1);
        }
    }
}

// ---------------------------------------------------------------------------
// Fused softmax + deformable bilinear sampling (R13 version, 122us) with
// fp16-split fused epilogue.
// ---------------------------------------------------------------------------
__global__ void __launch_bounds__(256)
sample_kernel(const float* __restrict__ value,
              const float* __restrict__ offs,
              const float* __restrict__ alog,
              const float* __restrict__ refp,
              uint4* __restrict__ msout_sp)
{
    __shared__ int4   sIdx[8][16];
    __shared__ float4 sWt [8][16];

    const int wid  = threadIdx.x >> 5;
    const int lane = threadIdx.x & 31;
    const int m    = wid;
    const int row  = blockIdx.x;
    const int b    = (row >= LQ) ? 1 : 0;

    // ---- softmax over 16 (l,p) logits ----
    const float* lg = alog + (size_t)row * 128 + m * 16;
    float v = (lane < 16) ? lg[lane] : -1e30f;
    float mx = v;
    #pragma unroll
    for (int o = 16; o; o >>= 1) mx = fmaxf(mx, __shfl_xor_sync(0xffffffffu, mx, o));
    float e = (lane < 16) ? expf(v - mx) : 0.f;
    float s = e;
    #pragma unroll
    for (int o = 16; o; o >>= 1) s += __shfl_xor_sync(0xffffffffu, s, o);
    const float inv = 1.f / s;

    // ---- per-point setup ----
    if (lane < 16) {
        const int l  = lane >> 2;
        const int H  = c_H[l];
        const int W  = c_W[l];
        const int st = c_ST[l];
        const float fW = (float)W, fH = (float)H;

        const float rx = refp[(row * 4 + l) * 2 + 0];
        const float ry = refp[(row * 4 + l) * 2 + 1];
        const float* od = offs + (size_t)row * 256 + m * 32 + lane * 2;
        const float ox = od[0], oy = od[1];

        const float x = fmaf(rx, fW, ox) - 0.5f;
        const float y = fmaf(ry, fH, oy) - 0.5f;

        const float x0f = floorf(x), y0f = floorf(y);
        const float fx = x - x0f, fy = y - y0f;
        const int ix = (int)x0f, iy = (int)y0f;

        const float lw = e * inv;
        float w00 = (1.f - fx) * (1.f - fy) * lw;
        float w01 = fx * (1.f - fy) * lw;
        float w10 = (1.f - fx) * fy * lw;
        float w11 = fx * fy * lw;

        const bool vx0 = (ix >= 0) && (ix < W);
        const bool vx1 = (ix + 1 >= 0) && (ix + 1 < W);
        const bool vy0 = (iy >= 0) && (iy < H);
        const bool vy1 = (iy + 1 >= 0) && (iy + 1 < H);
        if (!(vx0 && vy0)) w00 = 0.f;
        if (!(vx1 && vy0)) w01 = 0.f;
        if (!(vx0 && vy1)) w10 = 0.f;
        if (!(vx1 && vy1)) w11 = 0.f;

        const int cx0 = min(max(ix, 0), W - 1);
        const int cx1 = min(max(ix + 1, 0), W - 1);
        const int cy0 = min(max(iy, 0), H - 1);
        const int cy1 = min(max(iy + 1, 0), H - 1);
        const int r0 = st + cy0 * W;
        const int r1 = st + cy1 * W;

        sIdx[wid][lane] = make_int4((r0 + cx0) * 256, (r0 + cx1) * 256,
                                    (r1 + cx0) * 256, (r1 + cx1) * 256);
        sWt [wid][lane] = make_float4(w00, w01, w10, w11);
    }
    __syncwarp();

    // ---- gather: group g (8 lanes, float4 = 32 channels), 2 points/batch ----
    const int g  = lane >> 3;
    const int c4 = (lane & 7) * 4;
    const float* vb4 = value + (size_t)b * LQ * 256 + m * 32 + c4;

    float4 acc = make_float4(0.f, 0.f, 0.f, 0.f);
    #pragma unroll
    for (int h = 0; h < 2; h++) {
        const int pa = g * 4 + h * 2;
        const int4   Ia = sIdx[wid][pa];
        const int4   Ib = sIdx[wid][pa + 1];
        const float4 Wa_ = sWt[wid][pa];
        const float4 Wb_ = sWt[wid][pa + 1];
        float4 a0, a1, a2, a3, b0, b1, b2, b3;
        LDG4_NC(a0, vb4 + Ia.x);
        LDG4_NC(a1, vb4 + Ia.y);
        LDG4_NC(a2, vb4 + Ia.z);
        LDG4_NC(a3, vb4 + Ia.w);
        LDG4_NC(b0, vb4 + Ib.x);
        LDG4_NC(b1, vb4 + Ib.y);
        LDG4_NC(b2, vb4 + Ib.z);
        LDG4_NC(b3, vb4 + Ib.w);
        acc.x = fmaf(Wa_.x, a0.x, fmaf(Wa_.y, a1.x, fmaf(Wa_.z, a2.x, fmaf(Wa_.w, a3.x, acc.x))));
        acc.y = fmaf(Wa_.x, a0.y, fmaf(Wa_.y, a1.y, fmaf(Wa_.z, a2.y, fmaf(Wa_.w, a3.y, acc.y))));
        acc.z = fmaf(Wa_.x, a0.z, fmaf(Wa_.y, a1.z, fmaf(Wa_.z, a2.z, fmaf(Wa_.w, a3.z, acc.z))));
        acc.w = fmaf(Wa_.x, a0.w, fmaf(Wa_.y, a1.w, fmaf(Wa_.z, a2.w, fmaf(Wa_.w, a3.w, acc.w))));
        acc.x = fmaf(Wb_.x, b0.x, fmaf(Wb_.y, b1.x, fmaf(Wb_.z, b2.x, fmaf(Wb_.w, b3.x, acc.x))));
        acc.y = fmaf(Wb_.x, b0.y, fmaf(Wb_.y, b1.y, fmaf(Wb_.z, b2.y, fmaf(Wb_.w, b3.y, acc.y))));
        acc.z = fmaf(Wb_.x, b0.z, fmaf(Wb_.y, b1.z, fmaf(Wb_.z, b2.z, fmaf(Wb_.w, b3.z, acc.z))));
        acc.w = fmaf(Wb_.x, b0.w, fmaf(Wb_.y, b1.w, fmaf(Wb_.z, b2.w, fmaf(Wb_.w, b3.w, acc.w))));
    }

    // ---- butterfly over the 4 groups ----
    #pragma unroll
    for (int o = 8; o <= 16; o <<= 1) {
        acc.x += __shfl_xor_sync(0xffffffffu, acc.x, o);
        acc.y += __shfl_xor_sync(0xffffffffu, acc.y, o);
        acc.z += __shfl_xor_sync(0xffffffffu, acc.z, o);
        acc.w += __shfl_xor_sync(0xffffffffu, acc.w, o);
    }

    // ---- fused epilogue: emit fp16-split fragment slot directly ----
    {
        const int j  = lane & 7;
        const int sI = (j >> 2) & 1;
        const int tI = j & 3;
        const int src0 = 4 * sI + (tI >> 1);
        const int src1 = src0 + 2;

        float x0 = __shfl_sync(0xffffffffu, acc.x, src0);
        float y0 = __shfl_sync(0xffffffffu, acc.y, src0);
        float z0 = __shfl_sync(0xffffffffu, acc.z, src0);
        float w0 = __shfl_sync(0xffffffffu, acc.w, src0);
        float x1 = __shfl_sync(0xffffffffu, acc.x, src1);
        float y1 = __shfl_sync(0xffffffffu, acc.y, src1);
        float z1 = __shfl_sync(0xffffffffu, acc.z, src1);
        float w1 = __shfl_sync(0xffffffffu, acc.w, src1);

        const bool odd = (tI & 1);
        float2 p0 = odd ? make_float2(z0, w0) : make_float2(x0, y0);
        float2 p1 = odd ? make_float2(z1, w1) : make_float2(x1, y1);

        if (lane < 8)
            msout_sp[(size_t)row * 64 + m * 8 + j] = split_pack(p0, p1);
    }
}

// ---------------------------------------------------------------------------
// Launch: 5 graph-capturable kernel launches (single stream, R13 structure).
// ---------------------------------------------------------------------------
extern "C" void kernel_launch(void* const* d_in, const int* in_sizes, int n_in,
                              void* d_out, int out_size)
{
    (void)in_sizes; (void)n_in; (void)out_size;

    const float* query = (const float*)d_in[0];
    const float* refp  = (const float*)d_in[1];
    const float* inpf  = (const float*)d_in[2];
    const float* Wv = (const float*)d_in[4];
    const float* bv = (const float*)d_in[5];
    const float* Ws = (const float*)d_in[6];
    const float* bs = (const float*)d_in[7];
    const float* Wa = (const float*)d_in[8];
    const float* ba = (const float*)d_in[9];
    const float* Wo = (const float*)d_in[10];
    const float* bo = (const float*)d_in[11];
    float* out = (float*)d_out;

    float *value, *offs, *alog;
    uint4 *inpf_sp, *query_sp, *msout_sp, *Wv_sp, *Ws_sp, *Wa_sp, *Wo_sp;
    cudaGetSymbolAddress((void**)&value, g_value);
    cudaGetSymbolAddress((void**)&offs,  g_offs);
    cudaGetSymbolAddress((void**)&alog,  g_alog);
    cudaGetSymbolAddress((void**)&inpf_sp,  g_inpf_sp);
    cudaGetSymbolAddress((void**)&query_sp, g_query_sp);
    cudaGetSymbolAddress((void**)&msout_sp, g_msout_sp);
    cudaGetSymbolAddress((void**)&Wv_sp, g_Wv_sp);
    cudaGetSymbolAddress((void**)&Ws_sp, g_Ws_sp);
    cudaGetSymbolAddress((void**)&Wa_sp, g_Wa_sp);
    cudaGetSymbolAddress((void**)&Wo_sp, g_Wo_sp);

    cudaFuncSetAttribute(gemm_split, cudaFuncAttributeMaxDynamicSharedMemorySize,
                         GEMM_SMEM);

    const dim3 blk(256);
    const int  mTiles = (ROWS + 127) / 128;        // 192
    const int  aBlocks = ROWS * 64 / 256;          // 6120

    // 1) weights -> split fragment layout (tiny)
    convert_W4<<<dim3(64, 4), blk>>>(Wv, Wv_sp, 256, Ws, Ws_sp, 256,
                                     Wa, Wa_sp, 128, Wo, Wo_sp, 256);
    // 2) inpf + query -> split fragment layout
    convert_A2<<<dim3(aBlocks, 2), blk>>>(inpf, inpf_sp, query, query_sp, ROWS);
    // 3) value / offs / alog in ONE launch (y = 2 + 2 + 1 = 5, 128-wide tiles)
    gemm_split<<<dim3(mTiles, 5), blk, GEMM_SMEM>>>(
        inpf_sp,  Wv_sp, bv, value, 256, 2,
        query_sp, Ws_sp, bs, offs,  256, 2,
        query_sp, Wa_sp, ba, alog,  128,
        ROWS);
    // 4) fused softmax + sampling + fp16-split epilogue (writes msout_sp)
    sample_kernel<<<ROWS, blk>>>(value, offs, alog, refp, msout_sp);
    // 5) out = msout @ Wo + bo  (y = 2)
    gemm_split<<<dim3(mTiles, 2), blk, GEMM_SMEM>>>(
        msout_sp, Wo_sp, bo, out, 256, 2,
        msout_sp, Wo_sp, bo, out, 256, 0,
        msout_sp, Wo_sp, bo, out, 256,
        ROWS);
}

// round 16
// speedup vs baseline: 1.4492x; 1.0946x over previous
#include <cuda_runtime.h>
#include <cuda_bf16.h>
#include <cuda_fp16.h>
#include <math.h>
#include <stdint.h>

// ---------------------------------------------------------------------------
// Problem constants
// ---------------------------------------------------------------------------
#define BB   2
#define LQ   12240
#define DMO  256
#define MH   8
#define ROWS (BB * LQ)     // 24480

__device__ __constant__ int c_H[4]  = {96, 48, 24, 12};
__device__ __constant__ int c_W[4]  = {96, 48, 24, 12};
__device__ __constant__ int c_ST[4] = {0, 9216, 11520, 12096};

// ---------------------------------------------------------------------------
// Scratch (static device globals: allocation-free, graph-safe)
// ---------------------------------------------------------------------------
__device__ __half g_value_h[ROWS * DMO];   // value in fp16 (GEMM writes directly)
__device__ float  g_offs [ROWS * DMO];
__device__ float  g_alog [ROWS * 128];

// pre-split fp16 fragment-layout buffers (uint4 slots)
__device__ uint4 g_inpf_sp [ROWS * 64];
__device__ uint4 g_query_sp[ROWS * 64];
__device__ uint4 g_msout_sp[ROWS * 64];
__device__ uint4 g_Wv_sp[64 * 256];
__device__ uint4 g_Ws_sp[64 * 256];
__device__ uint4 g_Wa_sp[64 * 128];
__device__ uint4 g_Wo_sp[64 * 256];

// ---------------------------------------------------------------------------
// fp16 split helpers
// ---------------------------------------------------------------------------
__device__ __forceinline__ uint32_t h2u(__half2 h) {
    uint32_t u; *(__half2*)&u = h; return u;
}
__device__ __forceinline__ __half2 u2h(uint32_t u) {
    __half2 h; *(uint32_t*)&h = u; return h;
}

__device__ __forceinline__ uint4 split_pack(float2 p0, float2 p1) {
    __half2 H0 = __floats2half2_rn(p0.x, p0.y);     // .x (low) = even-k
    __half2 H1 = __floats2half2_rn(p1.x, p1.y);
    float2 hf0 = __half22float2(H0);
    float2 hf1 = __half22float2(H1);
    __half2 L0 = __floats2half2_rn(p0.x - hf0.x, p0.y - hf0.y);
    __half2 L1 = __floats2half2_rn(p1.x - hf1.x, p1.y - hf1.y);
    uint4 r;
    r.x = h2u(H0); r.y = h2u(L0); r.z = h2u(H1); r.w = h2u(L1);
    return r;
}

// m16n8k16 fp16 MMA
__device__ __forceinline__ void mma_f16(float4& c,
                                        uint32_t a0, uint32_t a1, uint32_t a2, uint32_t a3,
                                        uint32_t b0, uint32_t b1) {
    asm volatile(
        "mma.sync.aligned.m16n8k16.row.col.f32.f16.f16.f32 "
        "{%0,%1,%2,%3}, {%4,%5,%6,%7}, {%8,%9}, {%0,%1,%2,%3};"
        : "+f"(c.x), "+f"(c.y), "+f"(c.z), "+f"(c.w)
        : "r"(a0), "r"(a1), "r"(a2), "r"(a3), "r"(b0), "r"(b1));
}

__device__ __forceinline__ uint32_t smem_u32(const void* p) {
    uint32_t a;
    asm("{ .reg .u64 t; cvta.to.shared.u64 t, %1; cvt.u32.u64 %0, t; }"
        : "=r"(a) : "l"(p));
    return a;
}

__device__ __forceinline__ void cp16(uint32_t smem, const void* gmem, uint32_t sz) {
    asm volatile("cp.async.cg.shared.global [%0], [%1], 16, %2;"
                 :: "r"(smem), "l"(gmem), "r"(sz) : "memory");
}
#define CP_COMMIT() asm volatile("cp.async.commit_group;" ::: "memory")
#define CP_WAIT(n)  asm volatile("cp.async.wait_group %0;" :: "n"(n) : "memory")

// Ordered 8-byte read-only load (4 halves)
#define LDG2_NC(dst, ptr)                                                     \
    asm volatile("ld.global.nc.v2.u32 {%0,%1}, [%2];"                         \
                 : "=r"((dst).x), "=r"((dst).y) : "l"(ptr))

// ---------------------------------------------------------------------------
// Pre-convert A-style matrices [rows x 256] f32 -> fragment-layout uint4.
// ---------------------------------------------------------------------------
__global__ void __launch_bounds__(256)
convert_A2(const float* __restrict__ A0, uint4* __restrict__ D0,
           const float* __restrict__ A1, uint4* __restrict__ D1, int rows)
{
    const float* src = blockIdx.y ? A1 : A0;
    uint4*       dst = blockIdx.y ? D1 : D0;
    int g = blockIdx.x * 256 + threadIdx.x;
    if (g >= rows * 64) return;
    int row  = g >> 6;
    int rest = g & 63;
    int chunk = rest >> 3;
    int s = (rest >> 2) & 1;
    int t = rest & 3;
    const float* p = src + (size_t)row * 256 + chunk * 32 + s * 16 + 2 * t;
    float2 p0 = *(const float2*)p;
    float2 p1 = *(const float2*)(p + 8);
    dst[g] = split_pack(p0, p1);
}

// ---------------------------------------------------------------------------
// Pre-convert weights [256 x ncols] f32 -> B fragment layout.
// ---------------------------------------------------------------------------
__global__ void __launch_bounds__(256)
convert_W4(const float* __restrict__ W0, uint4* __restrict__ D0, int n0,
           const float* __restrict__ W1, uint4* __restrict__ D1, int n1,
           const float* __restrict__ W2, uint4* __restrict__ D2, int n2,
           const float* __restrict__ W3, uint4* __restrict__ D3, int n3)
{
    const float* Wm; uint4* D; int ncols;
    switch (blockIdx.y) {
        case 0:  Wm = W0; D = D0; ncols = n0; break;
        case 1:  Wm = W1; D = D1; ncols = n1; break;
        case 2:  Wm = W2; D = D2; ncols = n2; break;
        default: Wm = W3; D = D3; ncols = n3; break;
    }
    int g = blockIdx.x * 256 + threadIdx.x;
    if (g >= 64 * ncols) return;
    int n    = g % ncols;
    int rest = g / ncols;
    int chunk = rest >> 3;
    int s = (rest >> 2) & 1;
    int t = rest & 3;
    int k = chunk * 32 + s * 16 + 2 * t;
    const float* p = Wm + (size_t)k * ncols + n;
    float2 p0 = make_float2(p[0], p[ncols]);
    float2 p1 = make_float2(p[8 * ncols], p[9 * ncols]);
    D[(size_t)(chunk * ncols + n) * 8 + s * 4 + t] = split_pack(p0, p1);
}

// ---------------------------------------------------------------------------
// Pre-split fp16 GEMM + bias. Per-set flags: bit0 = add Al*Bh term (2-term
// split = full-A x Bh), bit1 = store output as fp16 (half2).
// Block tile 128x128, 8 warps = 4(M) x 2(N), warp tile 32x64, K chunk 32,
// double-buffered cp.async. Triple-set y-dispatch.
// ---------------------------------------------------------------------------
#define STAGE_U4   3072
#define GEMM_SMEM  (2 * STAGE_U4 * 16)   // 98304 B

__global__ void __launch_bounds__(256)
gemm_split(const uint4* __restrict__ A0, const uint4* __restrict__ P0,
           const float* __restrict__ b0, void* __restrict__ C0, int nc0, int yt0, int fl0,
           const uint4* __restrict__ A1, const uint4* __restrict__ P1,
           const float* __restrict__ b1, void* __restrict__ C1, int nc1, int yt1, int fl1,
           const uint4* __restrict__ A2, const uint4* __restrict__ P2,
           const float* __restrict__ b2, void* __restrict__ C2, int nc2, int fl2,
           int rows)
{
    extern __shared__ uint4 sm[];

    const int y = blockIdx.y;
    const uint4 *Asp, *Wsp;  const float* bias;  void* C;  int ncols, colBase, flags;
    if (y < yt0) {
        Asp = A0; Wsp = P0; bias = b0; C = C0; ncols = nc0; flags = fl0; colBase = y * 128;
    } else if (y < yt0 + yt1) {
        Asp = A1; Wsp = P1; bias = b1; C = C1; ncols = nc1; flags = fl1; colBase = (y - yt0) * 128;
    } else {
        Asp = A2; Wsp = P2; bias = b2; C = C2; ncols = nc2; flags = fl2; colBase = (y - yt0 - yt1) * 128;
    }
    const bool twoTerm = (flags & 1);
    const bool halfOut = (flags & 2);

    const int tid  = threadIdx.x;
    const int lane = tid & 31;
    const int wid  = tid >> 5;
    const int wm   = wid & 3;
    const int wn   = wid >> 2;
    const int r    = lane >> 2;
    const int tig  = lane & 3;
    const int rowBase = blockIdx.x * 128;

    const uint32_t smem_base = smem_u32(sm);
    const int a_row  = tid >> 3;
    const int a_slot = tid & 7;

    float4 acc[2][8];
    #pragma unroll
    for (int mt = 0; mt < 2; mt++)
        #pragma unroll
        for (int nt = 0; nt < 8; nt++)
            acc[mt][nt] = make_float4(0.f, 0.f, 0.f, 0.f);

#define LOAD_CHUNK(KB, ST)                                                    \
    do {                                                                      \
        const uint32_t _base = smem_base + (ST) * (STAGE_U4 * 16);            \
        _Pragma("unroll")                                                     \
        for (int it = 0; it < 4; it++) {                                      \
            int row  = a_row + it * 32;                                       \
            int grow = rowBase + row;                                         \
            cp16(_base + (uint32_t)(row * 12 + a_slot) * 16,                  \
                 Asp + ((size_t)grow * 64 + (KB) * 8 + a_slot),               \
                 (grow < rows) ? 16u : 0u);                                   \
        }                                                                     \
        _Pragma("unroll")                                                     \
        for (int it = 0; it < 4; it++) {                                      \
            int n = a_row + it * 32;                                          \
            cp16(_base + (uint32_t)(1536 + n * 12 + a_slot) * 16,             \
                 Wsp + ((size_t)((KB) * ncols + colBase + n) * 8 + a_slot), 16u); \
        }                                                                     \
        CP_COMMIT();                                                          \
    } while (0)

    LOAD_CHUNK(0, 0);

    for (int kb = 0; kb < 8; kb++) {
        if (kb < 7) {
            LOAD_CHUNK(kb + 1, (kb + 1) & 1);
            CP_WAIT(1);
        } else {
            CP_WAIT(0);
        }
        __syncthreads();

        const uint4* As4 = sm + (kb & 1) * STAGE_U4;
        const uint4* Bs4 = As4 + 1536;

        #pragma unroll
        for (int s = 0; s < 2; s++) {
            uint4 aw[2][2];
            #pragma unroll
            for (int mt = 0; mt < 2; mt++) {
                const int ar = wm * 32 + mt * 16 + r;
                aw[mt][0] = As4[ar * 12 + s * 4 + tig];
                aw[mt][1] = As4[(ar + 8) * 12 + s * 4 + tig];
            }
            #pragma unroll
            for (int nt = 0; nt < 8; nt++) {
                uint4 bw = Bs4[(wn * 64 + nt * 8 + r) * 12 + s * 4 + tig];
                #pragma unroll
                for (int mt = 0; mt < 2; mt++) {
                    mma_f16(acc[mt][nt], aw[mt][0].x, aw[mt][1].x, aw[mt][0].z, aw[mt][1].z, bw.x, bw.z);
                    if (twoTerm)
                        mma_f16(acc[mt][nt], aw[mt][0].y, aw[mt][1].y, aw[mt][0].w, aw[mt][1].w, bw.x, bw.z);
                }
            }
        }
        __syncthreads();
    }
#undef LOAD_CHUNK

    // ---- epilogue: +bias, float2 or half2 stores ----
    #pragma unroll
    for (int nt = 0; nt < 8; nt++) {
        const int col = colBase + wn * 64 + nt * 8 + tig * 2;
        const float bb0 = bias[col], bb1 = bias[col + 1];
        #pragma unroll
        for (int mt = 0; mt < 2; mt++) {
            const int row0 = rowBase + wm * 32 + mt * 16 + r;
            const float4 c4 = acc[mt][nt];
            if (halfOut) {
                __half* Ch = (__half*)C;
                if (row0 < rows)
                    *(uint32_t*)(Ch + (size_t)row0 * ncols + col) =
                        h2u(__floats2half2_rn(c4.x + bb0, c4.y + bb1));
                if (row0 + 8 < rows)
                    *(uint32_t*)(Ch + (size_t)(row0 + 8) * ncols + col) =
                        h2u(__floats2half2_rn(c4.z + bb0, c4.w + bb1));
            } else {
                float* Cf = (float*)C;
                if (row0 < rows)
                    *(float2*)(Cf + (size_t)row0 * ncols + col) =
                        make_float2(c4.x + bb0, c4.y + bb1);
                if (row0 + 8 < rows)
                    *(float2*)(Cf + (size_t)(row0 + 8) * ncols + col) =
                        make_float2(c4.z + bb0, c4.w + bb1);
            }
        }
    }
}

// ---------------------------------------------------------------------------
// Fused softmax + deformable bilinear sampling, fp16-value edition.
// value is fp16: each corner gather = 64B (8 lanes x uint2 of 4 halves).
// Per-point math in half2 (8 HFMA2), widened to float per point, float
// accumulation across points. Weights pre-broadcast to half2 in smem.
// Epilogue emits fp16-split msout fragments directly.
// ---------------------------------------------------------------------------
__global__ void __launch_bounds__(256)
sample_kernel(const __half* __restrict__ value,
              const float* __restrict__ offs,
              const float* __restrict__ alog,
              const float* __restrict__ refp,
              uint4* __restrict__ msout_sp)
{
    __shared__ int4  sIdx[8][16];
    __shared__ uint4 sWtH[8][16];

    const int wid  = threadIdx.x >> 5;
    const int lane = threadIdx.x & 31;
    const int m    = wid;
    const int row  = blockIdx.x;
    const int b    = (row >= LQ) ? 1 : 0;

    // ---- softmax over 16 (l,p) logits ----
    const float* lg = alog + (size_t)row * 128 + m * 16;
    float v = (lane < 16) ? lg[lane] : -1e30f;
    float mx = v;
    #pragma unroll
    for (int o = 16; o; o >>= 1) mx = fmaxf(mx, __shfl_xor_sync(0xffffffffu, mx, o));
    float e = (lane < 16) ? expf(v - mx) : 0.f;
    float s = e;
    #pragma unroll
    for (int o = 16; o; o >>= 1) s += __shfl_xor_sync(0xffffffffu, s, o);
    const float inv = 1.f / s;

    // ---- per-point setup ----
    if (lane < 16) {
        const int l  = lane >> 2;
        const int H  = c_H[l];
        const int W  = c_W[l];
        const int st = c_ST[l];
        const float fW = (float)W, fH = (float)H;

        const float rx = refp[(row * 4 + l) * 2 + 0];
        const float ry = refp[(row * 4 + l) * 2 + 1];
        const float* od = offs + (size_t)row * 256 + m * 32 + lane * 2;
        const float ox = od[0], oy = od[1];

        const float x = fmaf(rx, fW, ox) - 0.5f;
        const float y = fmaf(ry, fH, oy) - 0.5f;

        const float x0f = floorf(x), y0f = floorf(y);
        const float fx = x - x0f, fy = y - y0f;
        const int ix = (int)x0f, iy = (int)y0f;

        const float lw = e * inv;
        float w00 = (1.f - fx) * (1.f - fy) * lw;
        float w01 = fx * (1.f - fy) * lw;
        float w10 = (1.f - fx) * fy * lw;
        float w11 = fx * fy * lw;

        const bool vx0 = (ix >= 0) && (ix < W);
        const bool vx1 = (ix + 1 >= 0) && (ix + 1 < W);
        const bool vy0 = (iy >= 0) && (iy < H);
        const bool vy1 = (iy + 1 >= 0) && (iy + 1 < H);
        if (!(vx0 && vy0)) w00 = 0.f;
        if (!(vx1 && vy0)) w01 = 0.f;
        if (!(vx0 && vy1)) w10 = 0.f;
        if (!(vx1 && vy1)) w11 = 0.f;

        const int cx0 = min(max(ix, 0), W - 1);
        const int cx1 = min(max(ix + 1, 0), W - 1);
        const int cy0 = min(max(iy, 0), H - 1);
        const int cy1 = min(max(iy + 1, 0), H - 1);
        const int r0 = st + cy0 * W;
        const int r1 = st + cy1 * W;

        sIdx[wid][lane] = make_int4((r0 + cx0) * 256, (r0 + cx1) * 256,
                                    (r1 + cx0) * 256, (r1 + cx1) * 256);
        sWtH[wid][lane] = make_uint4(h2u(__floats2half2_rn(w00, w00)),
                                     h2u(__floats2half2_rn(w01, w01)),
                                     h2u(__floats2half2_rn(w10, w10)),
                                     h2u(__floats2half2_rn(w11, w11)));
    }
    __syncwarp();

    // ---- gather: group g (8 lanes x 4 half channels = 32ch), 2 pts/batch ----
    const int g  = lane >> 3;
    const int c4 = (lane & 7) * 4;
    const __half* vb = value + (size_t)b * LQ * 256 + m * 32 + c4;

    float4 accf = make_float4(0.f, 0.f, 0.f, 0.f);
    const __half2 hz = __floats2half2_rn(0.f, 0.f);

    #pragma unroll
    for (int h = 0; h < 2; h++) {
        const int pa = g * 4 + h * 2;
        const int4  Ia  = sIdx[wid][pa];
        const int4  Ib  = sIdx[wid][pa + 1];
        const uint4 Wta = sWtH[wid][pa];
        const uint4 Wtb = sWtH[wid][pa + 1];

        uint2 va0, va1, va2, va3, vb0, vb1, vb2, vb3;
        LDG2_NC(va0, vb + Ia.x);
        LDG2_NC(va1, vb + Ia.y);
        LDG2_NC(va2, vb + Ia.z);
        LDG2_NC(va3, vb + Ia.w);
        LDG2_NC(vb0, vb + Ib.x);
        LDG2_NC(vb1, vb + Ib.y);
        LDG2_NC(vb2, vb + Ib.z);
        LDG2_NC(vb3, vb + Ib.w);

        // point a: 8 HFMA2
        __half2 a0 = hz, a1 = hz;
        a0 = __hfma2(u2h(Wta.x), u2h(va0.x), a0); a1 = __hfma2(u2h(Wta.x), u2h(va0.y), a1);
        a0 = __hfma2(u2h(Wta.y), u2h(va1.x), a0); a1 = __hfma2(u2h(Wta.y), u2h(va1.y), a1);
        a0 = __hfma2(u2h(Wta.z), u2h(va2.x), a0); a1 = __hfma2(u2h(Wta.z), u2h(va2.y), a1);
        a0 = __hfma2(u2h(Wta.w), u2h(va3.x), a0); a1 = __hfma2(u2h(Wta.w), u2h(va3.y), a1);
        float2 fa0 = __half22float2(a0);
        float2 fa1 = __half22float2(a1);
        accf.x += fa0.x; accf.y += fa0.y; accf.z += fa1.x; accf.w += fa1.y;

        // point b: 8 HFMA2
        __half2 b0h = hz, b1h = hz;
        b0h = __hfma2(u2h(Wtb.x), u2h(vb0.x), b0h); b1h = __hfma2(u2h(Wtb.x), u2h(vb0.y), b1h);
        b0h = __hfma2(u2h(Wtb.y), u2h(vb1.x), b0h); b1h = __hfma2(u2h(Wtb.y), u2h(vb1.y), b1h);
        b0h = __hfma2(u2h(Wtb.z), u2h(vb2.x), b0h); b1h = __hfma2(u2h(Wtb.z), u2h(vb2.y), b1h);
        b0h = __hfma2(u2h(Wtb.w), u2h(vb3.x), b0h); b1h = __hfma2(u2h(Wtb.w), u2h(vb3.y), b1h);
        float2 fb0 = __half22float2(b0h);
        float2 fb1 = __half22float2(b1h);
        accf.x += fb0.x; accf.y += fb0.y; accf.z += fb1.x; accf.w += fb1.y;
    }

    // ---- butterfly over the 4 groups ----
    #pragma unroll
    for (int o = 8; o <= 16; o <<= 1) {
        accf.x += __shfl_xor_sync(0xffffffffu, accf.x, o);
        accf.y += __shfl_xor_sync(0xffffffffu, accf.y, o);
        accf.z += __shfl_xor_sync(0xffffffffu, accf.z, o);
        accf.w += __shfl_xor_sync(0xffffffffu, accf.w, o);
    }

    // ---- fused epilogue: emit fp16-split fragment slot directly ----
    {
        const int j  = lane & 7;
        const int sI = (j >> 2) & 1;
        const int tI = j & 3;
        const int src0 = 4 * sI + (tI >> 1);
        const int src1 = src0 + 2;

        float x0 = __shfl_sync(0xffffffffu, accf.x, src0);
        float y0 = __shfl_sync(0xffffffffu, accf.y, src0);
        float z0 = __shfl_sync(0xffffffffu, accf.z, src0);
        float w0 = __shfl_sync(0xffffffffu, accf.w, src0);
        float x1 = __shfl_sync(0xffffffffu, accf.x, src1);
        float y1 = __shfl_sync(0xffffffffu, accf.y, src1);
        float z1 = __shfl_sync(0xffffffffu, accf.z, src1);
        float w1 = __shfl_sync(0xffffffffu, accf.w, src1);

        const bool odd = (tI & 1);
        float2 p0 = odd ? make_float2(z0, w0) : make_float2(x0, y0);
        float2 p1 = odd ? make_float2(z1, w1) : make_float2(x1, y1);

        if (lane < 8)
            msout_sp[(size_t)row * 64 + m * 8 + j] = split_pack(p0, p1);
    }
}

// ---------------------------------------------------------------------------
// Launch: 5 graph-capturable kernel launches (single stream).
// ---------------------------------------------------------------------------
extern "C" void kernel_launch(void* const* d_in, const int* in_sizes, int n_in,
                              void* d_out, int out_size)
{
    (void)in_sizes; (void)n_in; (void)out_size;

    const float* query = (const float*)d_in[0];
    const float* refp  = (const float*)d_in[1];
    const float* inpf  = (const float*)d_in[2];
    const float* Wv = (const float*)d_in[4];
    const float* bv = (const float*)d_in[5];
    const float* Ws = (const float*)d_in[6];
    const float* bs = (const float*)d_in[7];
    const float* Wa = (const float*)d_in[8];
    const float* ba = (const float*)d_in[9];
    const float* Wo = (const float*)d_in[10];
    const float* bo = (const float*)d_in[11];
    float* out = (float*)d_out;

    __half* value_h;
    float *offs, *alog;
    uint4 *inpf_sp, *query_sp, *msout_sp, *Wv_sp, *Ws_sp, *Wa_sp, *Wo_sp;
    cudaGetSymbolAddress((void**)&value_h, g_value_h);
    cudaGetSymbolAddress((void**)&offs,  g_offs);
    cudaGetSymbolAddress((void**)&alog,  g_alog);
    cudaGetSymbolAddress((void**)&inpf_sp,  g_inpf_sp);
    cudaGetSymbolAddress((void**)&query_sp, g_query_sp);
    cudaGetSymbolAddress((void**)&msout_sp, g_msout_sp);
    cudaGetSymbolAddress((void**)&Wv_sp, g_Wv_sp);
    cudaGetSymbolAddress((void**)&Ws_sp, g_Ws_sp);
    cudaGetSymbolAddress((void**)&Wa_sp, g_Wa_sp);
    cudaGetSymbolAddress((void**)&Wo_sp, g_Wo_sp);

    cudaFuncSetAttribute(gemm_split, cudaFuncAttributeMaxDynamicSharedMemorySize,
                         GEMM_SMEM);

    const dim3 blk(256);
    const int  mTiles = (ROWS + 127) / 128;        // 192
    const int  aBlocks = ROWS * 64 / 256;          // 6120

    // 1) weights -> split fragment layout (tiny)
    convert_W4<<<dim3(64, 4), blk>>>(Wv, Wv_sp, 256, Ws, Ws_sp, 256,
                                     Wa, Wa_sp, 128, Wo, Wo_sp, 256);
    // 2) inpf + query -> split fragment layout
    convert_A2<<<dim3(aBlocks, 2), blk>>>(inpf, inpf_sp, query, query_sp, ROWS);
    // 3) value (2-term, fp16 out) / offs (1-term) / alog (1-term), one launch
    gemm_split<<<dim3(mTiles, 5), blk, GEMM_SMEM>>>(
        inpf_sp,  Wv_sp, bv, (void*)value_h, 256, 2, /*flags*/ 3,
        query_sp, Ws_sp, bs, (void*)offs,    256, 2, /*flags*/ 0,
        query_sp, Wa_sp, ba, (void*)alog,    128,    /*flags*/ 0,
        ROWS);
    // 4) fused softmax + fp16 sampling + fp16-split epilogue (writes msout_sp)
    sample_kernel<<<ROWS, blk>>>(value_h, offs, alog, refp, msout_sp);
    // 5) out = msout @ Wo + bo  (2-term, f32 out)
    gemm_split<<<dim3(mTiles, 2), blk, GEMM_SMEM>>>(
        msout_sp, Wo_sp, bo, (void*)out, 256, 2, /*flags*/ 1,
        msout_sp, Wo_sp, bo, (void*)out, 256, 0, /*flags*/ 1,
        msout_sp, Wo_sp, bo, (void*)out, 256,    /*flags*/ 1,
        ROWS);
}